// round 12
// baseline (speedup 1.0000x reference)
#include <cuda_runtime.h>
#include <cuda_fp16.h>
#include <math.h>
#include <stdint.h>

// Problem shapes (fixed by the dataset)
#define T_MAX 262144
#define B_MAX 4096
#define F_DIM 128
#define H_DIM 256
#define C_DIM 512
#define KV_DIM 512

// ---------------------------------------------------------------------------
// Scratch (allocation-free rule: __device__ globals)
// ---------------------------------------------------------------------------
__device__ __half g_objh[(size_t)T_MAX * F_DIM];      // 64 MB
__device__ __half g_ctxh[(size_t)B_MAX * C_DIM];      // 4 MB
__device__ __half g_h1 [(size_t)T_MAX * H_DIM];       // 128 MB
__device__ __half g_h2 [(size_t)T_MAX * H_DIM];       // 128 MB
__device__ __half g_vh [(size_t)T_MAX * H_DIM];       // 128 MB (v half of kv, fp16)
__device__ float  g_q  [(size_t)B_MAX * H_DIM];       // 4 MB
__device__ float  g_lp [2 * (size_t)T_MAX];           // 2 MB logit partials
__device__ __half g_Wt1[H_DIM * F_DIM];               // W1^T [N][K] fp16
__device__ __half g_Wt2[H_DIM * H_DIM];
__device__ __half g_Wt3[KV_DIM * H_DIM];
__device__ __half g_Wtq[H_DIM * C_DIM];
__device__ int    g_segstart[B_MAX + 1];

// ---------------------------------------------------------------------------
// Helpers
// ---------------------------------------------------------------------------
__device__ __forceinline__ uint32_t smem_u32(const void* p) {
    uint32_t a;
    asm("{ .reg .u64 t; cvta.to.shared.u64 t, %1; cvt.u32.u64 %0, t; }" : "=r"(a) : "l"(p));
    return a;
}

#define CP_ASYNC16(dst, src) \
    asm volatile("cp.async.cg.shared.global [%0], [%1], 16;" :: "r"(dst), "l"(src) : "memory")
#define CP_COMMIT() asm volatile("cp.async.commit_group;" ::: "memory")
#define CP_WAIT0()  asm volatile("cp.async.wait_group 0;" ::: "memory")
#define CP_WAIT1()  asm volatile("cp.async.wait_group 1;" ::: "memory")

#define LDSM_X4(r0, r1, r2, r3, addr) \
    asm volatile("ldmatrix.sync.aligned.m8n8.x4.shared.b16 {%0,%1,%2,%3}, [%4];" \
        : "=r"(r0), "=r"(r1), "=r"(r2), "=r"(r3) : "r"(addr))

// mma.sync m16n8k16 fp16 -> fp32 accumulate
__device__ __forceinline__ void mma_fp16(float* c, const uint32_t* a, const uint32_t* b) {
    asm volatile(
        "mma.sync.aligned.m16n8k16.row.col.f32.f16.f16.f32 "
        "{%0,%1,%2,%3}, {%4,%5,%6,%7}, {%8,%9}, {%0,%1,%2,%3};"
        : "+f"(c[0]), "+f"(c[1]), "+f"(c[2]), "+f"(c[3])
        : "r"(a[0]), "r"(a[1]), "r"(a[2]), "r"(a[3]), "r"(b[0]), "r"(b[1]));
}

// Stage layout: BK=64 halves (128 B data/row), row stride 144 B (bank-free).
#define ROW_B 144
#define STAGE_BYTES (2 * 128 * ROW_B)        // 36864 B
#define NSTAGE 3
#define GEMM_SMEM (NSTAGE * STAGE_BYTES)     // 110592 B -> 2 CTA/SM
#define PGRID 296                            // persistent grid: 2 x 148 SMs

// ---------------------------------------------------------------------------
// Chunk primitives
// ---------------------------------------------------------------------------
__device__ __forceinline__ void load_chunk(
    uint32_t sb, int s, const __half* __restrict__ Asrc,
    const __half* __restrict__ Bsrc, int K, int tid)
{
    uint32_t abase = sb + (uint32_t)s * STAGE_BYTES;
    uint32_t bbase = abase + 128 * ROW_B;
#pragma unroll
    for (int i = 0; i < 4; i++) {
        int idx = tid + i * 256;
        int row = idx >> 3, k16 = idx & 7;   // 8 x 16B chunks per 128B row
        CP_ASYNC16(abase + (uint32_t)(row * ROW_B + k16 * 16), Asrc + (size_t)row * K + k16 * 8);
        CP_ASYNC16(bbase + (uint32_t)(row * ROW_B + k16 * 16), Bsrc + (size_t)row * K + k16 * 8);
    }
    CP_COMMIT();
}

__device__ __forceinline__ void compute_chunk(
    uint32_t Ab, int wm, int wn, int lm_r, int lm_k, float acc[2][8][4])
{
    const uint32_t Bb = Ab + 128 * ROW_B;
#pragma unroll
    for (int ks = 0; ks < 4; ks++) {         // four k16 steps per BK=64
        uint32_t a[2][4], b[8][2];
#pragma unroll
        for (int mf = 0; mf < 2; mf++) {
            uint32_t addr = Ab + (uint32_t)((wm * 32 + mf * 16 + lm_r) * ROW_B + ks * 32) + lm_k;
            LDSM_X4(a[mf][0], a[mf][1], a[mf][2], a[mf][3], addr);
        }
#pragma unroll
        for (int p = 0; p < 4; p++) {
            uint32_t addr = Bb + (uint32_t)((wn * 64 + p * 16 + lm_r) * ROW_B + ks * 32) + lm_k;
            LDSM_X4(b[2 * p][0], b[2 * p + 1][0], b[2 * p][1], b[2 * p + 1][1], addr);
        }
#pragma unroll
        for (int mf = 0; mf < 2; mf++)
#pragma unroll
            for (int nf = 0; nf < 8; nf++)
                mma_fp16(acc[mf][nf], a[mf], b[nf]);
    }
}

// ---------------------------------------------------------------------------
// Persistent GEMM: MODE 0 = fp32 out, MODE 1 = fp16 out. Continuous ring.
// Tile t: m = t >> logNN, n = t & (2^logNN - 1). CTA owns tiles cta + j*grid.
// ---------------------------------------------------------------------------
template <bool RELU, int MODE>
__global__ __launch_bounds__(256, 2) void gemm_persist(
    const __half* __restrict__ A, const __half* __restrict__ Wt,
    const float* __restrict__ bias,
    float* __restrict__ Cf, __half* __restrict__ Ch,
    int nTiles, int logNN, int K, int lognk)
{
    extern __shared__ uint32_t dyn[];
    const uint32_t sb = smem_u32(dyn);
    const int tid = threadIdx.x;
    const int wid = tid >> 5, lane = tid & 31;
    const int g = lane >> 2, tg = lane & 3;
    const int wm = wid >> 1, wn = wid & 1;
    const int lm_r = lane & 15;
    const int lm_k = (lane >> 4) * 16;

    const int grid = gridDim.x, cta = blockIdx.x;
    const int nkm1 = (1 << lognk) - 1;
    const int nNm1 = (1 << logNN) - 1;
    const int N = (nNm1 + 1) * 128;

    const int myTiles = (cta < nTiles) ? ((nTiles - 1 - cta) / grid + 1) : 0;
    const int tot = myTiles << lognk;
    if (tot == 0) return;

    auto src = [&](int u, const __half*& As, const __half*& Bs) {
        int j = u >> lognk, c = u & nkm1;
        int tile = cta + j * grid;
        int m = tile >> logNN, n = tile & nNm1;
        As = A + ((size_t)m * 128) * K + c * 64;
        Bs = Wt + ((size_t)n * 128) * K + c * 64;
    };

    float acc[2][8][4];
#pragma unroll
    for (int mf = 0; mf < 2; mf++)
#pragma unroll
        for (int nf = 0; nf < 8; nf++)
#pragma unroll
            for (int j = 0; j < 4; j++) acc[mf][nf][j] = 0.f;

    {
        const __half *As, *Bs;
        src(0, As, Bs); load_chunk(sb, 0, As, Bs, K, tid);
        if (tot > 1) { src(1, As, Bs); load_chunk(sb, 1, As, Bs, K, tid); }
    }

    int s = 0;                                // ring stage for chunk u
    for (int u = 0; u < tot; u++) {
        if (u + 1 < tot) CP_WAIT1(); else CP_WAIT0();
        __syncthreads();
        if (u + 2 < tot) {
            const __half *As, *Bs;
            src(u + 2, As, Bs);
            int s2 = s + 2; if (s2 >= NSTAGE) s2 -= NSTAGE;
            load_chunk(sb, s2, As, Bs, K, tid);
        }
        compute_chunk(sb + (uint32_t)s * STAGE_BYTES, wm, wn, lm_r, lm_k, acc);
        if (++s == NSTAGE) s = 0;

        if ((u & nkm1) == nkm1) {
            // epilogue for this tile
            int tile = cta + (u >> lognk) * grid;
            size_t m0 = (size_t)(tile >> logNN) * 128;
            int n0 = (tile & nNm1) * 128;
#pragma unroll
            for (int mf = 0; mf < 2; mf++) {
                size_t row0 = m0 + wm * 32 + mf * 16 + g;
#pragma unroll
                for (int nf = 0; nf < 8; nf++) {
                    int col = n0 + wn * 64 + nf * 8 + tg * 2;
                    float b0 = __ldg(bias + col), b1 = __ldg(bias + col + 1);
                    float v0 = acc[mf][nf][0] + b0;
                    float v1 = acc[mf][nf][1] + b1;
                    float v2 = acc[mf][nf][2] + b0;
                    float v3 = acc[mf][nf][3] + b1;
                    if (RELU) { v0 = fmaxf(v0, 0.f); v1 = fmaxf(v1, 0.f); v2 = fmaxf(v2, 0.f); v3 = fmaxf(v3, 0.f); }
                    if (MODE == 0) {
                        *reinterpret_cast<float2*>(Cf + row0 * N + col)       = make_float2(v0, v1);
                        *reinterpret_cast<float2*>(Cf + (row0 + 8) * N + col) = make_float2(v2, v3);
                    } else {
                        *reinterpret_cast<__half2*>(Ch + row0 * N + col)       = __floats2half2_rn(v0, v1);
                        *reinterpret_cast<__half2*>(Ch + (row0 + 8) * N + col) = __floats2half2_rn(v2, v3);
                    }
                }
            }
#pragma unroll
            for (int mf = 0; mf < 2; mf++)
#pragma unroll
                for (int nf = 0; nf < 8; nf++)
#pragma unroll
                    for (int j = 0; j < 4; j++) acc[mf][nf][j] = 0.f;
        }
    }
}

// ---------------------------------------------------------------------------
// Persistent kv GEMM with fused logits. nN=4 (k,k,v,v), K=256, nk=4.
// k-tiles (n<2): dot fp32 accumulators against q[seg[t]] (direct L2 loads)
// v-tiles: fp16 store
// ---------------------------------------------------------------------------
__global__ __launch_bounds__(256, 2) void gemm_kv_persist(
    const __half* __restrict__ A, const __half* __restrict__ Wt,
    const float* __restrict__ bias,
    __half* __restrict__ v_out, float* __restrict__ lpart,
    const float* __restrict__ q, const int* __restrict__ seg,
    int nTiles, int M)
{
    extern __shared__ uint32_t dyn[];
    __shared__ float s_logit[128];
    const uint32_t sb = smem_u32(dyn);
    const int tid = threadIdx.x;
    const int wid = tid >> 5, lane = tid & 31;
    const int g = lane >> 2, tg = lane & 3;
    const int wm = wid >> 1, wn = wid & 1;
    const int lm_r = lane & 15;
    const int lm_k = (lane >> 4) * 16;

    const int grid = gridDim.x, cta = blockIdx.x;
    constexpr int K = H_DIM;                  // 256
    constexpr int lognk = 2, nkm1 = 3;
    constexpr int logNN = 2, nNm1 = 3;

    const int myTiles = (cta < nTiles) ? ((nTiles - 1 - cta) / grid + 1) : 0;
    const int tot = myTiles << lognk;
    if (tot == 0) return;

    if (tid < 128) s_logit[tid] = 0.f;        // first loop sync publishes this

    auto src = [&](int u, const __half*& As, const __half*& Bs) {
        int j = u >> lognk, c = u & nkm1;
        int tile = cta + j * grid;
        int m = tile >> logNN, n = tile & nNm1;
        As = A + ((size_t)m * 128) * K + c * 64;
        Bs = Wt + ((size_t)n * 128) * K + c * 64;
    };

    float acc[2][8][4];
#pragma unroll
    for (int mf = 0; mf < 2; mf++)
#pragma unroll
        for (int nf = 0; nf < 8; nf++)
#pragma unroll
            for (int j = 0; j < 4; j++) acc[mf][nf][j] = 0.f;

    {
        const __half *As, *Bs;
        src(0, As, Bs); load_chunk(sb, 0, As, Bs, K, tid);
        if (tot > 1) { src(1, As, Bs); load_chunk(sb, 1, As, Bs, K, tid); }
    }

    int s = 0;
    for (int u = 0; u < tot; u++) {
        if (u + 1 < tot) CP_WAIT1(); else CP_WAIT0();
        __syncthreads();
        if (u + 2 < tot) {
            const __half *As, *Bs;
            src(u + 2, As, Bs);
            int s2 = s + 2; if (s2 >= NSTAGE) s2 -= NSTAGE;
            load_chunk(sb, s2, As, Bs, K, tid);
        }
        compute_chunk(sb + (uint32_t)s * STAGE_BYTES, wm, wn, lm_r, lm_k, acc);
        if (++s == NSTAGE) s = 0;

        if ((u & nkm1) == nkm1) {
            int tile = cta + (u >> lognk) * grid;
            size_t t0 = (size_t)(tile >> logNN) * 128;
            int n = tile & nNm1;
            int n0 = n * 128;

            if (n < 2) {
                // k-tile: logits partials; q rows fetched directly (L2-hot)
#pragma unroll
                for (int mf = 0; mf < 2; mf++) {
                    int rA = wm * 32 + mf * 16 + g;
                    int rB = rA + 8;
                    const float* qA = q + (size_t)__ldg(seg + t0 + rA) * H_DIM + n0;
                    const float* qB = q + (size_t)__ldg(seg + t0 + rB) * H_DIM + n0;
                    float pA = 0.f, pB = 0.f;
#pragma unroll
                    for (int nf = 0; nf < 8; nf++) {
                        int cq = wn * 64 + nf * 8 + tg * 2;
                        int col = n0 + cq;
                        float bb0 = __ldg(bias + col), bb1 = __ldg(bias + col + 1);
                        float2 qa = *reinterpret_cast<const float2*>(qA + cq);
                        float2 qb = *reinterpret_cast<const float2*>(qB + cq);
                        pA = fmaf(acc[mf][nf][0] + bb0, qa.x, pA);
                        pA = fmaf(acc[mf][nf][1] + bb1, qa.y, pA);
                        pB = fmaf(acc[mf][nf][2] + bb0, qb.x, pB);
                        pB = fmaf(acc[mf][nf][3] + bb1, qb.y, pB);
                    }
                    pA += __shfl_xor_sync(0xffffffffu, pA, 1);
                    pA += __shfl_xor_sync(0xffffffffu, pA, 2);
                    pB += __shfl_xor_sync(0xffffffffu, pB, 1);
                    pB += __shfl_xor_sync(0xffffffffu, pB, 2);
                    if (tg == 0) {
                        atomicAdd(s_logit + rA, pA);
                        atomicAdd(s_logit + rB, pB);
                    }
                }
                __syncthreads();
                if (tid < 128) {
                    lpart[(size_t)n * M + t0 + tid] = s_logit[tid] * 0.0625f;
                    s_logit[tid] = 0.f;       // next tile's atomics ordered by loop sync
                }
            } else {
                // v-tile: bias + fp16 store
#pragma unroll
                for (int mf = 0; mf < 2; mf++) {
                    size_t r0 = t0 + wm * 32 + mf * 16 + g;
#pragma unroll
                    for (int nf = 0; nf < 8; nf++) {
                        int col = n0 + wn * 64 + nf * 8 + tg * 2;
                        float bb0 = __ldg(bias + col), bb1 = __ldg(bias + col + 1);
                        int vc = col - 256;
                        *reinterpret_cast<__half2*>(v_out + r0 * H_DIM + vc) =
                            __floats2half2_rn(acc[mf][nf][0] + bb0, acc[mf][nf][1] + bb1);
                        *reinterpret_cast<__half2*>(v_out + (r0 + 8) * H_DIM + vc) =
                            __floats2half2_rn(acc[mf][nf][2] + bb0, acc[mf][nf][3] + bb1);
                    }
                }
            }
#pragma unroll
            for (int mf = 0; mf < 2; mf++)
#pragma unroll
                for (int nf = 0; nf < 8; nf++)
#pragma unroll
                    for (int j = 0; j < 4; j++) acc[mf][nf][j] = 0.f;
        }
    }
}

// ---------------------------------------------------------------------------
// One merged prep kernel: obj cvt | ctx cvt | 4 weight transposes | segstart
// ---------------------------------------------------------------------------
#define OBJ_BLK   (T_MAX * F_DIM / 4 / 256)            // 32768
#define CTX_BLK   (B_MAX * C_DIM / 4 / 256)            // 512
#define W1_BLK    (F_DIM * H_DIM / 256)                // 128
#define W2_BLK    (H_DIM * H_DIM / 256)                // 256
#define W3_BLK    (H_DIM * KV_DIM / 256)               // 512
#define WQ_BLK    (C_DIM * H_DIM / 256)                // 512
#define SEG_BLK   (T_MAX / 256)                        // 1024
#define PREP_BLOCKS (OBJ_BLK + CTX_BLK + W1_BLK + W2_BLK + W3_BLK + WQ_BLK + SEG_BLK)

__device__ __forceinline__ void cvt_range(const float* in, __half* out, int i) {
    float4 v = reinterpret_cast<const float4*>(in)[i];
    reinterpret_cast<__half2*>(out)[i * 2]     = __floats2half2_rn(v.x, v.y);
    reinterpret_cast<__half2*>(out)[i * 2 + 1] = __floats2half2_rn(v.z, v.w);
}
__device__ __forceinline__ void tr_range(const float* W, __half* Wt, int K, int N, int i) {
    int k = i / N, n = i - k * N;
    Wt[(size_t)n * K + k] = __float2half_rn(W[i]);
}

__global__ void prep_all(
    const float* __restrict__ objects, const float* __restrict__ context,
    const float* __restrict__ W1, const float* __restrict__ W2,
    const float* __restrict__ W3, const float* __restrict__ Wq,
    const int* __restrict__ seg, int T, int B)
{
    int b = blockIdx.x;
    int t = threadIdx.x;
    if (b < OBJ_BLK) { cvt_range(objects, g_objh, b * 256 + t); return; }
    b -= OBJ_BLK;
    if (b < CTX_BLK) { cvt_range(context, g_ctxh, b * 256 + t); return; }
    b -= CTX_BLK;
    if (b < W1_BLK) { tr_range(W1, g_Wt1, F_DIM, H_DIM, b * 256 + t); return; }
    b -= W1_BLK;
    if (b < W2_BLK) { tr_range(W2, g_Wt2, H_DIM, H_DIM, b * 256 + t); return; }
    b -= W2_BLK;
    if (b < W3_BLK) { tr_range(W3, g_Wt3, H_DIM, KV_DIM, b * 256 + t); return; }
    b -= W3_BLK;
    if (b < WQ_BLK) { tr_range(Wq, g_Wtq, C_DIM, H_DIM, b * 256 + t); return; }
    b -= WQ_BLK;
    {   // segstart
        int i = b * 256 + t;
        if (i == 0) { g_segstart[seg[0]] = 0; g_segstart[B] = T; }
        if (i > 0 && i < T) {
            int s = seg[i];
            if (s != seg[i - 1]) g_segstart[s] = i;
        }
    }
}

// ---------------------------------------------------------------------------
// Per-segment softmax + weighted value sum. One 256-thread block per segment.
// ---------------------------------------------------------------------------
__global__ __launch_bounds__(256) void segreduce_kernel(
    const float* __restrict__ lp0, const float* __restrict__ lp1,
    float* __restrict__ emb, float* __restrict__ wout)
{
    const int s = blockIdx.x;
    const int s0 = g_segstart[s];
    const int s1 = g_segstart[s + 1];
    const int tid = threadIdx.x;

    __shared__ float red[8];
    __shared__ float bcast;

    float m = -INFINITY;
    for (int t = s0 + tid; t < s1; t += 256) m = fmaxf(m, lp0[t] + lp1[t]);
#pragma unroll
    for (int o = 16; o; o >>= 1) m = fmaxf(m, __shfl_xor_sync(0xffffffffu, m, o));
    if ((tid & 31) == 0) red[tid >> 5] = m;
    __syncthreads();
    if (tid == 0) {
        float mm = red[0];
#pragma unroll
        for (int i = 1; i < 8; i++) mm = fmaxf(mm, red[i]);
        bcast = mm;
    }
    __syncthreads();
    m = bcast;
    __syncthreads();

    float z = 0.f;
    for (int t = s0 + tid; t < s1; t += 256) z += __expf(lp0[t] + lp1[t] - m);
#pragma unroll
    for (int o = 16; o; o >>= 1) z += __shfl_xor_sync(0xffffffffu, z, o);
    if ((tid & 31) == 0) red[tid >> 5] = z;
    __syncthreads();
    if (tid == 0) {
        float zz = 0.f;
#pragma unroll
        for (int i = 0; i < 8; i++) zz += red[i];
        bcast = zz;
    }
    __syncthreads();
    const float inv = 1.f / bcast;
    __syncthreads();

    for (int t = s0 + tid; t < s1; t += 256) wout[t] = __expf(lp0[t] + lp1[t] - m) * inv;
    __syncthreads();

    float acc = 0.f;
    for (int t = s0; t < s1; t++) {
        float w = wout[t];
        acc = fmaf(w, __half2float(g_vh[(size_t)t * H_DIM + tid]), acc);
    }
    emb[(size_t)s * H_DIM + tid] = acc;
}

// ---------------------------------------------------------------------------
// Launch
// ---------------------------------------------------------------------------
extern "C" void kernel_launch(void* const* d_in, const int* in_sizes, int n_in,
                              void* d_out, int out_size)
{
    const float* objects = (const float*)d_in[0];
    const float* context = (const float*)d_in[1];
    const int*   seg     = (const int*)  d_in[2];
    const float* W1 = (const float*)d_in[3];
    const float* b1 = (const float*)d_in[4];
    const float* W2 = (const float*)d_in[5];
    const float* b2 = (const float*)d_in[6];
    const float* W3 = (const float*)d_in[7];
    const float* b3 = (const float*)d_in[8];
    const float* Wq = (const float*)d_in[9];
    const float* bq = (const float*)d_in[10];

    const int T = in_sizes[2];                 // 262144
    const int B = in_sizes[1] / C_DIM;         // 4096

    float* out = (float*)d_out;
    float* emb_out = out;
    float* w_out   = out + (size_t)B * H_DIM;

    __half *p_objh, *p_ctxh, *p_h1, *p_h2, *p_vh, *p_w1, *p_w2, *p_w3, *p_wq;
    float *p_q, *p_lp;
    cudaGetSymbolAddress((void**)&p_objh, g_objh);
    cudaGetSymbolAddress((void**)&p_ctxh, g_ctxh);
    cudaGetSymbolAddress((void**)&p_h1, g_h1);
    cudaGetSymbolAddress((void**)&p_h2, g_h2);
    cudaGetSymbolAddress((void**)&p_vh, g_vh);
    cudaGetSymbolAddress((void**)&p_q,  g_q);
    cudaGetSymbolAddress((void**)&p_lp, g_lp);
    cudaGetSymbolAddress((void**)&p_w1, g_Wt1);
    cudaGetSymbolAddress((void**)&p_w2, g_Wt2);
    cudaGetSymbolAddress((void**)&p_w3, g_Wt3);
    cudaGetSymbolAddress((void**)&p_wq, g_Wtq);

    cudaFuncSetAttribute(gemm_persist<false, 0>, cudaFuncAttributeMaxDynamicSharedMemorySize, GEMM_SMEM);
    cudaFuncSetAttribute(gemm_persist<true, 1>,  cudaFuncAttributeMaxDynamicSharedMemorySize, GEMM_SMEM);
    cudaFuncSetAttribute(gemm_kv_persist, cudaFuncAttributeMaxDynamicSharedMemorySize, GEMM_SMEM);

    // All prep in one launch
    prep_all<<<PREP_BLOCKS, 256>>>(objects, context, W1, W2, W3, Wq, seg, T, B);

    // q = context @ Wq + bq  [4096,512]->[4096,256] fp32
    // Tiles = (B/128) * (256/128) = 32 * 2 = 64   (round-10 bug: passed 8)
    gemm_persist<false, 0><<<64, 256, GEMM_SMEM>>>(
        p_ctxh, p_wq, bq, p_q, nullptr, /*nTiles=*/(B / 128) * 2, /*logNN=*/1, C_DIM, /*lognk=*/3);
    // h1 = relu(objects @ W1 + b1)  fp16 out (4096 tiles, nk=2)
    gemm_persist<true, 1><<<PGRID, 256, GEMM_SMEM>>>(
        p_objh, p_w1, b1, nullptr, p_h1, /*nTiles=*/(T / 128) * 2, 1, F_DIM, 1);
    // h2 = relu(h1 @ W2 + b2)  fp16 out (4096 tiles, nk=4)
    gemm_persist<true, 1><<<PGRID, 256, GEMM_SMEM>>>(
        p_h1, p_w2, b2, nullptr, p_h2, (T / 128) * 2, 1, H_DIM, 2);
    // kv: k-tiles -> fused logit partials, v-tiles -> g_vh (8192 tiles, nk=4)
    gemm_kv_persist<<<PGRID, 256, GEMM_SMEM>>>(
        p_h2, p_w3, b3, p_vh, p_lp, p_q, seg, (T / 128) * 4, T);

    segreduce_kernel<<<B, 256>>>(p_lp, p_lp + T, emb_out, w_out);
}